// round 8
// baseline (speedup 1.0000x reference)
#include <cuda_runtime.h>

// SphKernel: out[b,v,p,n,c] = g_n(r) * Y_c(rotate(frame, normalize(patch)))
// B=4, V=4096, P=64, NR=3, C=16. 1,048,576 points; 48 f32 out/point (201 MB).
//
// R8: settled facts: __stcs streaming stores everywhere (wb path costs +5.7us,
// L2 residency across replays never materializes); wall is store-drain
// limited at ~6 TB/s. This round removes the last structural overheads:
//  - persistent grid (2432 blocks = 152 SM x 16 resident), grid-stride loop
//    over 32-point warp-tiles (no 3.5-wave block churn).
//  - warp-autonomous staging: per-warp smem slice + __syncwarp only; warps
//    free-run, smoothing the store stream.

#define TPB 128
#define WPB 4                         // warps per block
#define PT_F4 5                       // float4 chunks per point
#define PT_STRIDE 20                  // floats per point row
#define GRID_BLOCKS 2432              // 152 SMs * 16 blocks
#define TILES 32768                   // 1,048,576 pts / 32 per warp-tile

__global__ __launch_bounds__(TPB, 16)
void sph_kernel(const float* __restrict__ patches,
                const float* __restrict__ frames,
                const float* __restrict__ r,
                float* __restrict__ out)
{
    __shared__ float4 sh4[WPB][32 * PT_F4];       // 4 * 2560 B = 10240 B

    const int lane = threadIdx.x & 31;
    const int wid  = threadIdx.x >> 5;
    const int gwarp  = blockIdx.x * WPB + wid;
    const int nwarps = GRID_BLOCKS * WPB;         // 9728

    float4* ws4 = sh4[wid];
    float*  ws  = reinterpret_cast<float*>(ws4);
    float4* out4 = reinterpret_cast<float4*>(out);

    for (int tile = gwarp; tile < TILES; tile += nwarps) {
        const int pt = tile * 32 + lane;          // global point index
        const int fi = pt >> 6;                   // frame index (P = 64)

        // ---- load & normalize direction ----
        const float px = __ldg(patches + 3 * pt + 0);
        const float py = __ldg(patches + 3 * pt + 1);
        const float pz = __ldg(patches + 3 * pt + 2);
        const float sq  = px * px + py * py + pz * pz;
        const float inv = rsqrtf(fmaxf(sq, 1e-12f));
        const float dx = px * inv, dy = py * inv, dz = pz * inv;

        // ---- rotate into local frame ----
        const float* F = frames + 9 * fi;         // half-warp-uniform
        const float x = __ldg(F + 0) * dx + __ldg(F + 3) * dy + __ldg(F + 6) * dz;
        const float y = __ldg(F + 1) * dx + __ldg(F + 4) * dy + __ldg(F + 7) * dz;
        const float z = __ldg(F + 2) * dx + __ldg(F + 5) * dy + __ldg(F + 8) * dz;

        // ---- spherical harmonics (reference channel order) ----
        const float x2 = x * x, y2 = y * y, z2 = z * z;
        const float xy = x * y, yz = y * z, zx = z * x;

        float4* row4 = ws4 + lane * PT_F4;
        row4[0] = make_float4(
            0.28209479177387814f,
            0.4886025119029199f * z,
            0.31539156525252005f * (2.f * z2 - x2 - y2),
            0.3731763325901154f * z * (2.f * z2 - 3.f * x2 - 3.f * y2));
        row4[1] = make_float4(
            0.4886025119029199f * x,
            0.4886025119029199f * y,
            1.0925484305920792f * zx,
            1.0925484305920792f * yz);
        row4[2] = make_float4(
            0.4570457994644658f * x * (4.f * z2 - x2 - y2),
            0.4570457994644658f * y * (4.f * z2 - x2 - y2),
            0.5462742152960396f * (x2 - y2),
            1.0925484305920792f * xy);
        row4[3] = make_float4(
            1.4453057213202771f * z * (x2 - y2),
            2.8906114426405543f * xy * z,
            0.5900435899266435f * x * (x2 - 3.f * y2),
            0.5900435899266435f * y * (3.f * x2 - y2));

        // ---- gaussian shells ----
        const float rv = __ldg(r + pt);
        const float K = -2.772588722239781f;      // 4 * ln(0.5)
        const float d1 = rv - 0.5f, d2 = rv - 1.0f;
        const float g0 = __expf(K * rv * rv);
        const float g1 = __expf(K * d1 * d1);
        const float g2 = __expf(K * d2 * d2);
        const float ginv = __fdividef(1.0f, g0 + g1 + g2);
        row4[4] = make_float4(g0 * ginv, g1 * ginv, g2 * ginv, 0.0f);

        __syncwarp();

        // ---- coalesced streaming float4 write-out (384 f4 per tile) ----
        const size_t base = (size_t)tile * 384;
#pragma unroll
        for (int k = 0; k < 12; k++) {
            const int f4 = k * 32 + lane;
            const int p  = f4 / 12;
            const int r4 = f4 - p * 12;
            const float4 Yv = ws4[p * PT_F4 + (r4 & 3)];
            const float g   = ws[p * PT_STRIDE + 16 + (r4 >> 2)];
            __stcs(out4 + base + f4,
                   make_float4(g * Yv.x, g * Yv.y, g * Yv.z, g * Yv.w));
        }

        __syncwarp();   // WAR: next iteration overwrites this warp's slice
    }
}

extern "C" void kernel_launch(void* const* d_in, const int* in_sizes, int n_in,
                              void* d_out, int out_size)
{
    const float* patches = (const float*)d_in[0];  // [4,4096,64,3]
    const float* frames  = (const float*)d_in[1];  // [4,4096,3,3]
    const float* r       = (const float*)d_in[2];  // [4,4096,64]
    float* out = (float*)d_out;                    // [4,4096,64,3,16]

    sph_kernel<<<GRID_BLOCKS, TPB>>>(patches, frames, r, out);
}

// round 9
// speedup vs baseline: 1.0595x; 1.0595x over previous
#include <cuda_runtime.h>

// SphKernel: out[b,v,p,n,c] = g_n(r) * Y_c(rotate(frame, normalize(patch)))
// B=4, V=4096, P=64, NR=3, C=16. 1,048,576 points; 48 f32 out/point (201 MB).
//
// R9 = R4 (best wall 33.3us: 128tpb, 16 blocks/SM, streaming stores) with the
// write-out upgraded to 256-bit streaming stores (st.global.cs.v8.f32,
// sm_100+). Same bytes, half the STG/LDS instructions; floor-probe against
// the ~6 TB/s HBM write-drain ceiling established in R4-R8.

#define TPB 128
#define PT_F4 5                      // float4 chunks per point
#define PT_STRIDE 20                 // floats per point row
#define VEC8_PER_BLOCK (TPB * 6)     // 768 float8 per block (24576 B)

__device__ __forceinline__ void stg_cs_v8(float* p,
                                          float a0, float a1, float a2, float a3,
                                          float a4, float a5, float a6, float a7)
{
    asm volatile("st.global.cs.v8.f32 [%0], {%1,%2,%3,%4,%5,%6,%7,%8};"
                 :: "l"(p), "f"(a0), "f"(a1), "f"(a2), "f"(a3),
                    "f"(a4), "f"(a5), "f"(a6), "f"(a7)
                 : "memory");
}

__global__ __launch_bounds__(TPB, 16)
void sph_kernel(const float* __restrict__ patches,
                const float* __restrict__ frames,
                const float* __restrict__ r,
                float* __restrict__ out)
{
    __shared__ float4 sh4[TPB * PT_F4];           // 10240 B
    float* sh = reinterpret_cast<float*>(sh4);

    const int tid = threadIdx.x;
    const int pt  = blockIdx.x * TPB + tid;       // global point index
    const int fi  = pt >> 6;                      // frame index (P = 64)

    // ---- load & normalize direction ----
    const float px = __ldg(patches + 3 * pt + 0);
    const float py = __ldg(patches + 3 * pt + 1);
    const float pz = __ldg(patches + 3 * pt + 2);
    const float sq  = px * px + py * py + pz * pz;
    const float inv = rsqrtf(fmaxf(sq, 1e-12f));
    const float dx = px * inv, dy = py * inv, dz = pz * inv;

    // ---- rotate into local frame: proj_j = sum_i F[i][j] * d_i ----
    const float* F = frames + 9 * fi;             // warp-uniform -> broadcast
    const float x = __ldg(F + 0) * dx + __ldg(F + 3) * dy + __ldg(F + 6) * dz;
    const float y = __ldg(F + 1) * dx + __ldg(F + 4) * dy + __ldg(F + 7) * dz;
    const float z = __ldg(F + 2) * dx + __ldg(F + 5) * dy + __ldg(F + 8) * dz;

    // ---- spherical harmonics (reference channel order) ----
    const float x2 = x * x, y2 = y * y, z2 = z * z;
    const float xy = x * y, yz = y * z, zx = z * x;

    float4* row4 = sh4 + tid * PT_F4;
    row4[0] = make_float4(
        0.28209479177387814f,                                   // Y00
        0.4886025119029199f * z,                                // Y10
        0.31539156525252005f * (2.f * z2 - x2 - y2),            // Y20
        0.3731763325901154f * z * (2.f * z2 - 3.f * x2 - 3.f * y2)); // Y30
    row4[1] = make_float4(
        0.4886025119029199f * x,                                // Y1_10
        0.4886025119029199f * y,                                // Y1_11
        1.0925484305920792f * zx,                               // Y2_10
        1.0925484305920792f * yz);                              // Y2_11
    row4[2] = make_float4(
        0.4570457994644658f * x * (4.f * z2 - x2 - y2),         // Y3_10
        0.4570457994644658f * y * (4.f * z2 - x2 - y2),         // Y3_11
        0.5462742152960396f * (x2 - y2),                        // Y2_20
        1.0925484305920792f * xy);                              // Y2_21
    row4[3] = make_float4(
        1.4453057213202771f * z * (x2 - y2),                    // Y3_20
        2.8906114426405543f * xy * z,                           // Y3_21
        0.5900435899266435f * x * (x2 - 3.f * y2),              // Y3_30
        0.5900435899266435f * y * (3.f * x2 - y2));             // Y3_31

    // ---- gaussian shells: centers {0, 0.5, 1}, normalized ----
    const float rv = __ldg(r + pt);
    const float K = -2.772588722239781f;          // 4 * ln(0.5)
    const float d1 = rv - 0.5f, d2 = rv - 1.0f;
    const float g0 = __expf(K * rv * rv);
    const float g1 = __expf(K * d1 * d1);
    const float g2 = __expf(K * d2 * d2);
    const float ginv = __fdividef(1.0f, g0 + g1 + g2);
    row4[4] = make_float4(g0 * ginv, g1 * ginv, g2 * ginv, 0.0f);

    __syncthreads();

    // ---- coalesced 256-bit streaming write-out ----
    // float8 index f8 covers floats [8*f8, 8*f8+8). 6 float8 per point.
    const size_t base8 = (size_t)blockIdx.x * VEC8_PER_BLOCK;
#pragma unroll
    for (int k = 0; k < 6; k++) {
        const int f8 = k * TPB + tid;       // float8 index within block tile
        const int p  = f8 / 6;              // point within block
        const int r8 = f8 - p * 6;
        const int shell = r8 >> 1;          // 0..2
        const int cg    = (r8 & 1) << 1;    // Y quad pair base: 0 or 2
        const float4 Ya = sh4[p * PT_F4 + cg];
        const float4 Yb = sh4[p * PT_F4 + cg + 1];
        const float g   = sh[p * PT_STRIDE + 16 + shell];
        stg_cs_v8(out + (base8 + f8) * 8,
                  g * Ya.x, g * Ya.y, g * Ya.z, g * Ya.w,
                  g * Yb.x, g * Yb.y, g * Yb.z, g * Yb.w);
    }
}

extern "C" void kernel_launch(void* const* d_in, const int* in_sizes, int n_in,
                              void* d_out, int out_size)
{
    const float* patches = (const float*)d_in[0];  // [4,4096,64,3]
    const float* frames  = (const float*)d_in[1];  // [4,4096,3,3]
    const float* r       = (const float*)d_in[2];  // [4,4096,64]
    float* out = (float*)d_out;                    // [4,4096,64,3,16]

    const int total_points = in_sizes[2];          // 1,048,576
    const int blocks = total_points / TPB;         // 8192

    sph_kernel<<<blocks, TPB>>>(patches, frames, r, out);
}

// round 10
// speedup vs baseline: 1.2242x; 1.1555x over previous
#include <cuda_runtime.h>

// SphKernel: out[b,v,p,n,c] = g_n(r) * Y_c(rotate(frame, normalize(patch)))
// B=4, V=4096, P=64, NR=3, C=16. 1,048,576 points; 48 f32 out/point (201 MB).
//
// R10 = R4 (best wall 33.3us: 128tpb, 16 blocks/SM, __stcs float4 streaming
// stores — the ONLY variable that moves wall time across R3-R9) with one
// isolated change: warp-autonomous staging. Each warp stages its 32 points in
// a private smem slice and syncs with __syncwarp, so warps start draining
// stores immediately instead of waiting on a block-wide barrier.
// NOT using: st.v8 (.cs hint silently dropped -> write-back band, R9),
// persistent grid (serializes, R8), write-back anywhere (R3/R5/R7).

#define TPB 128
#define WPB 4                        // warps per block
#define PT_F4 5                      // float4 chunks per point
#define PT_STRIDE 20                 // floats per point row

__global__ __launch_bounds__(TPB, 16)
void sph_kernel(const float* __restrict__ patches,
                const float* __restrict__ frames,
                const float* __restrict__ r,
                float* __restrict__ out)
{
    __shared__ float4 sh4[WPB][32 * PT_F4];       // 4 x 2560 B = 10240 B

    const int lane = threadIdx.x & 31;
    const int wid  = threadIdx.x >> 5;
    const int pt   = blockIdx.x * TPB + threadIdx.x;   // global point index
    const int fi   = pt >> 6;                          // frame index (P = 64)

    float4* ws4 = sh4[wid];
    float*  ws  = reinterpret_cast<float*>(ws4);

    // ---- load & normalize direction ----
    const float px = __ldg(patches + 3 * pt + 0);
    const float py = __ldg(patches + 3 * pt + 1);
    const float pz = __ldg(patches + 3 * pt + 2);
    const float sq  = px * px + py * py + pz * pz;
    const float inv = rsqrtf(fmaxf(sq, 1e-12f));
    const float dx = px * inv, dy = py * inv, dz = pz * inv;

    // ---- rotate into local frame: proj_j = sum_i F[i][j] * d_i ----
    const float* F = frames + 9 * fi;             // half-warp-uniform -> broadcast
    const float x = __ldg(F + 0) * dx + __ldg(F + 3) * dy + __ldg(F + 6) * dz;
    const float y = __ldg(F + 1) * dx + __ldg(F + 4) * dy + __ldg(F + 7) * dz;
    const float z = __ldg(F + 2) * dx + __ldg(F + 5) * dy + __ldg(F + 8) * dz;

    // ---- spherical harmonics (reference channel order) ----
    const float x2 = x * x, y2 = y * y, z2 = z * z;
    const float xy = x * y, yz = y * z, zx = z * x;

    float4* row4 = ws4 + lane * PT_F4;
    row4[0] = make_float4(
        0.28209479177387814f,                                   // Y00
        0.4886025119029199f * z,                                // Y10
        0.31539156525252005f * (2.f * z2 - x2 - y2),            // Y20
        0.3731763325901154f * z * (2.f * z2 - 3.f * x2 - 3.f * y2)); // Y30
    row4[1] = make_float4(
        0.4886025119029199f * x,                                // Y1_10
        0.4886025119029199f * y,                                // Y1_11
        1.0925484305920792f * zx,                               // Y2_10
        1.0925484305920792f * yz);                              // Y2_11
    row4[2] = make_float4(
        0.4570457994644658f * x * (4.f * z2 - x2 - y2),         // Y3_10
        0.4570457994644658f * y * (4.f * z2 - x2 - y2),         // Y3_11
        0.5462742152960396f * (x2 - y2),                        // Y2_20
        1.0925484305920792f * xy);                              // Y2_21
    row4[3] = make_float4(
        1.4453057213202771f * z * (x2 - y2),                    // Y3_20
        2.8906114426405543f * xy * z,                           // Y3_21
        0.5900435899266435f * x * (x2 - 3.f * y2),              // Y3_30
        0.5900435899266435f * y * (3.f * x2 - y2));             // Y3_31

    // ---- gaussian shells: centers {0, 0.5, 1}, normalized ----
    const float rv = __ldg(r + pt);
    const float K = -2.772588722239781f;          // 4 * ln(0.5)
    const float d1 = rv - 0.5f, d2 = rv - 1.0f;
    const float g0 = __expf(K * rv * rv);
    const float g1 = __expf(K * d1 * d1);
    const float g2 = __expf(K * d2 * d2);
    const float ginv = __fdividef(1.0f, g0 + g1 + g2);
    row4[4] = make_float4(g0 * ginv, g1 * ginv, g2 * ginv, 0.0f);

    __syncwarp();   // warp-private slice: only this warp's lanes must be done

    // ---- coalesced streaming float4 write-out, per warp (384 f4) ----
    float4* out4 = reinterpret_cast<float4*>(out);
    // warp's 32 points start at float4 index (blockIdx*128 + wid*32) * 12
    const size_t base = ((size_t)blockIdx.x * TPB + wid * 32) * 12;
#pragma unroll
    for (int k = 0; k < 12; k++) {
        const int f4 = k * 32 + lane;       // float4 index within warp tile
        const int p  = f4 / 12;             // point within warp (0..31)
        const int r4 = f4 - p * 12;
        const float4 Yv = ws4[p * PT_F4 + (r4 & 3)];
        const float g   = ws[p * PT_STRIDE + 16 + (r4 >> 2)];
        __stcs(out4 + base + f4,
               make_float4(g * Yv.x, g * Yv.y, g * Yv.z, g * Yv.w));
    }
}

extern "C" void kernel_launch(void* const* d_in, const int* in_sizes, int n_in,
                              void* d_out, int out_size)
{
    const float* patches = (const float*)d_in[0];  // [4,4096,64,3]
    const float* frames  = (const float*)d_in[1];  // [4,4096,3,3]
    const float* r       = (const float*)d_in[2];  // [4,4096,64]
    float* out = (float*)d_out;                    // [4,4096,64,3,16]

    const int total_points = in_sizes[2];          // 1,048,576
    const int blocks = total_points / TPB;         // 8192

    sph_kernel<<<blocks, TPB>>>(patches, frames, r, out);
}